// round 1
// baseline (speedup 1.0000x reference)
#include <cuda_runtime.h>
#include <cstdint>

#define TOKS 16384
#define HDIM 1024
#define IDIM 2048
#define NE   8

// ---------------- scratch (static device memory; no allocations) ----------------
__device__ int   g_cnt[16];
__device__ int   g_tok[NE * TOKS];
__device__ float g_wt [NE * TOKS];
// hidden activations: 9 expert slots (8 routed + shared at slot 8), capacity TOKS rows each
__device__ float g_hact[(size_t)(NE + 1) * TOKS * IDIM];

// ---------------- helpers ----------------
__device__ __forceinline__ uint32_t f2tf(float f) {
    uint32_t r;
    asm("cvt.rna.tf32.f32 %0, %1;" : "=r"(r) : "f"(f));
    return r;
}

__device__ __forceinline__ void mma_tf32(float* c,
                                         uint32_t a0, uint32_t a1, uint32_t a2, uint32_t a3,
                                         uint32_t b0, uint32_t b1) {
    asm volatile(
        "mma.sync.aligned.m16n8k8.row.col.f32.tf32.tf32.f32 "
        "{%0,%1,%2,%3}, {%4,%5,%6,%7}, {%8,%9}, {%0,%1,%2,%3};\n"
        : "+f"(c[0]), "+f"(c[1]), "+f"(c[2]), "+f"(c[3])
        : "r"(a0), "r"(a1), "r"(a2), "r"(a3), "r"(b0), "r"(b1));
}

// ---------------- kernel 0: zero counters ----------------
__global__ void zero_cnt_kernel() {
    if (threadIdx.x < 16) g_cnt[threadIdx.x] = 0;
}

// ---------------- kernel 1: router (sigmoid top-2) ----------------
// one warp per token; Wr staged in smem
__global__ void router_kernel(const float* __restrict__ x,
                              const float* __restrict__ Wr,
                              const float* __restrict__ rb) {
    __shared__ float sWr[NE][HDIM];
    int tid = threadIdx.x;
    for (int i = tid * 4; i < NE * HDIM; i += blockDim.x * 4) {
        *(float4*)&sWr[0][i] = *(const float4*)&Wr[i];
    }
    __syncthreads();

    int wid = tid >> 5, lane = tid & 31;
    int t = blockIdx.x * 8 + wid;
    const float* xr = x + (size_t)t * HDIM;

    float acc[NE];
#pragma unroll
    for (int e = 0; e < NE; e++) acc[e] = 0.f;

    for (int k = lane; k < HDIM; k += 32) {
        float xv = xr[k];
#pragma unroll
        for (int e = 0; e < NE; e++) acc[e] += xv * sWr[e][k];
    }
#pragma unroll
    for (int e = 0; e < NE; e++) {
#pragma unroll
        for (int off = 16; off > 0; off >>= 1)
            acc[e] += __shfl_xor_sync(0xffffffffu, acc[e], off);
    }

    if (lane == 0) {
        float best1 = -1e30f, best2 = -1e30f;
        int e1 = -1, e2 = -1;
#pragma unroll
        for (int e = 0; e < NE; e++) {
            float l = acc[e] + rb[e];
            if (l > best1) { best2 = best1; e2 = e1; best1 = l; e1 = e; }
            else if (l > best2) { best2 = l; e2 = e; }
        }
        float w1 = 1.f / (1.f + __expf(-best1));
        float w2 = 1.f / (1.f + __expf(-best2));
        int p1 = atomicAdd(&g_cnt[e1], 1);
        g_tok[e1 * TOKS + p1] = t;  g_wt[e1 * TOKS + p1] = w1;
        int p2 = atomicAdd(&g_cnt[e2], 1);
        g_tok[e2 * TOKS + p2] = t;  g_wt[e2 * TOKS + p2] = w2;
    }
}

// ---------------- kernel 2: fused gate+up GEMM, silu(g)*u epilogue ----------------
// BM=128, BN=64 (x2 matrices), BK=16, 256 threads, warp grid 4(M) x 2(N), warp tile 32x32
#define GU_BM 128
#define GU_BN 64
#define GU_BK 16
#define GU_LD (GU_BK + 4)

__global__ __launch_bounds__(256, 2) void gateup_kernel(
    const float* __restrict__ x,
    const float* __restrict__ Wg_s, const float* __restrict__ Wu_s,
    const float* __restrict__ Wg,   const float* __restrict__ Wu) {

    __shared__ uint32_t sA[GU_BM][GU_LD];
    __shared__ uint32_t sG[GU_BN][GU_LD];
    __shared__ uint32_t sU[GU_BN][GU_LD];
    __shared__ int sTok[GU_BM];

    int e = blockIdx.z;
    int rows = (e == NE) ? TOKS : g_cnt[e];
    int m0 = blockIdx.y * GU_BM;
    if (m0 >= rows) return;
    int n0 = blockIdx.x * GU_BN;

    const float* Bg = (e == NE) ? Wg_s : Wg + (size_t)e * IDIM * HDIM;
    const float* Bu = (e == NE) ? Wu_s : Wu + (size_t)e * IDIM * HDIM;

    int tid = threadIdx.x;
    for (int m = tid; m < GU_BM; m += 256) {
        int r = m0 + m;
        sTok[m] = (r < rows) ? ((e == NE) ? r : g_tok[e * TOKS + r]) : -1;
    }
    __syncthreads();

    int wid = tid >> 5, lane = tid & 31;
    int wm = (wid & 3) * 32;
    int wn = (wid >> 2) * 32;

    float accg[2][4][4], accu[2][4][4];
#pragma unroll
    for (int mt = 0; mt < 2; mt++)
#pragma unroll
        for (int nt = 0; nt < 4; nt++)
#pragma unroll
            for (int i = 0; i < 4; i++) { accg[mt][nt][i] = 0.f; accu[mt][nt][i] = 0.f; }

    for (int k0 = 0; k0 < HDIM; k0 += GU_BK) {
        __syncthreads();
        // load A tile (gathered token rows), 512 float4 / 256 threads
#pragma unroll
        for (int it = 0; it < 2; it++) {
            int idx = tid + it * 256;
            int m = idx >> 2, c4 = (idx & 3) * 4;
            int tok = sTok[m];
            float4 v = make_float4(0.f, 0.f, 0.f, 0.f);
            if (tok >= 0) v = *(const float4*)&x[(size_t)tok * HDIM + k0 + c4];
            sA[m][c4 + 0] = f2tf(v.x); sA[m][c4 + 1] = f2tf(v.y);
            sA[m][c4 + 2] = f2tf(v.z); sA[m][c4 + 3] = f2tf(v.w);
        }
        // load Wg/Wu tiles, 256 float4 each
        {
            int n = tid >> 2, c4 = (tid & 3) * 4;
            size_t off = (size_t)(n0 + n) * HDIM + k0 + c4;
            float4 vg = *(const float4*)&Bg[off];
            sG[n][c4 + 0] = f2tf(vg.x); sG[n][c4 + 1] = f2tf(vg.y);
            sG[n][c4 + 2] = f2tf(vg.z); sG[n][c4 + 3] = f2tf(vg.w);
            float4 vu = *(const float4*)&Bu[off];
            sU[n][c4 + 0] = f2tf(vu.x); sU[n][c4 + 1] = f2tf(vu.y);
            sU[n][c4 + 2] = f2tf(vu.z); sU[n][c4 + 3] = f2tf(vu.w);
        }
        __syncthreads();

#pragma unroll
        for (int kk = 0; kk < 2; kk++) {
            int kb = kk * 8;
            uint32_t a[2][4];
#pragma unroll
            for (int mt = 0; mt < 2; mt++) {
                int r = wm + mt * 16 + (lane >> 2);
                a[mt][0] = sA[r][kb + (lane & 3)];
                a[mt][1] = sA[r + 8][kb + (lane & 3)];
                a[mt][2] = sA[r][kb + (lane & 3) + 4];
                a[mt][3] = sA[r + 8][kb + (lane & 3) + 4];
            }
#pragma unroll
            for (int nt = 0; nt < 4; nt++) {
                int nb = wn + nt * 8 + (lane >> 2);
                uint32_t bg0 = sG[nb][kb + (lane & 3)];
                uint32_t bg1 = sG[nb][kb + (lane & 3) + 4];
                uint32_t bu0 = sU[nb][kb + (lane & 3)];
                uint32_t bu1 = sU[nb][kb + (lane & 3) + 4];
#pragma unroll
                for (int mt = 0; mt < 2; mt++) {
                    mma_tf32(accg[mt][nt], a[mt][0], a[mt][1], a[mt][2], a[mt][3], bg0, bg1);
                    mma_tf32(accu[mt][nt], a[mt][0], a[mt][1], a[mt][2], a[mt][3], bu0, bu1);
                }
            }
        }
    }

    // epilogue: hact = silu(g) * u
    size_t hbase = (size_t)e * TOKS * IDIM;
#pragma unroll
    for (int mt = 0; mt < 2; mt++) {
#pragma unroll
        for (int nt = 0; nt < 4; nt++) {
            int col = n0 + wn + nt * 8 + 2 * (lane & 3);
#pragma unroll
            for (int half = 0; half < 2; half++) {
                int r = m0 + wm + mt * 16 + (lane >> 2) + half * 8;
                if (r < rows) {
                    float g0 = accg[mt][nt][half * 2 + 0];
                    float g1 = accg[mt][nt][half * 2 + 1];
                    float u0 = accu[mt][nt][half * 2 + 0];
                    float u1 = accu[mt][nt][half * 2 + 1];
                    float h0 = g0 / (1.f + __expf(-g0)) * u0;
                    float h1 = g1 / (1.f + __expf(-g1)) * u1;
                    *(float2*)&g_hact[hbase + (size_t)r * IDIM + col] = make_float2(h0, h1);
                }
            }
        }
    }
}

// ---------------- kernel 3: down GEMM ----------------
// BM=128, BN=128, BK=16, 256 threads, warp grid 4(M) x 2(N), warp tile 32x64
#define D_BM 128
#define D_BN 128
#define D_BK 16
#define D_LD (D_BK + 4)

__global__ __launch_bounds__(256, 2) void down_kernel(
    const float* __restrict__ Wd_s, const float* __restrict__ Wd,
    float* __restrict__ out, int shared_mode) {

    __shared__ uint32_t sA[D_BM][D_LD];
    __shared__ uint32_t sB[D_BN][D_LD];
    __shared__ int   sTok[D_BM];
    __shared__ float sW[D_BM];

    int e = shared_mode ? NE : blockIdx.z;
    int rows = shared_mode ? TOKS : g_cnt[e];
    int m0 = blockIdx.y * D_BM;
    if (m0 >= rows) return;
    int n0 = blockIdx.x * D_BN;

    const float* Bw = shared_mode ? Wd_s : Wd + (size_t)e * HDIM * IDIM;

    int tid = threadIdx.x, wid = tid >> 5, lane = tid & 31;
    for (int m = tid; m < D_BM; m += 256) {
        int r = m0 + m;
        if (r < rows) {
            sTok[m] = shared_mode ? r : g_tok[e * TOKS + r];
            sW[m]   = shared_mode ? 1.f : g_wt[e * TOKS + r];
        } else {
            sTok[m] = -1; sW[m] = 0.f;
        }
    }

    int wm = (wid & 3) * 32;
    int wn = (wid >> 2) * 64;

    float acc[2][8][4];
#pragma unroll
    for (int mt = 0; mt < 2; mt++)
#pragma unroll
        for (int nt = 0; nt < 8; nt++)
#pragma unroll
            for (int i = 0; i < 4; i++) acc[mt][nt][i] = 0.f;

    const float* Arow = g_hact + ((size_t)e * TOKS + m0) * IDIM;

    for (int k0 = 0; k0 < IDIM; k0 += D_BK) {
        __syncthreads();
#pragma unroll
        for (int it = 0; it < 2; it++) {
            int idx = tid + it * 256;
            int m = idx >> 2, c4 = (idx & 3) * 4;
            float4 v = *(const float4*)&Arow[(size_t)m * IDIM + k0 + c4];
            sA[m][c4 + 0] = f2tf(v.x); sA[m][c4 + 1] = f2tf(v.y);
            sA[m][c4 + 2] = f2tf(v.z); sA[m][c4 + 3] = f2tf(v.w);
        }
#pragma unroll
        for (int it = 0; it < 2; it++) {
            int idx = tid + it * 256;
            int n = idx >> 2, c4 = (idx & 3) * 4;
            float4 v = *(const float4*)&Bw[(size_t)(n0 + n) * IDIM + k0 + c4];
            sB[n][c4 + 0] = f2tf(v.x); sB[n][c4 + 1] = f2tf(v.y);
            sB[n][c4 + 2] = f2tf(v.z); sB[n][c4 + 3] = f2tf(v.w);
        }
        __syncthreads();

#pragma unroll
        for (int kk = 0; kk < 2; kk++) {
            int kb = kk * 8;
            uint32_t a[2][4];
#pragma unroll
            for (int mt = 0; mt < 2; mt++) {
                int r = wm + mt * 16 + (lane >> 2);
                a[mt][0] = sA[r][kb + (lane & 3)];
                a[mt][1] = sA[r + 8][kb + (lane & 3)];
                a[mt][2] = sA[r][kb + (lane & 3) + 4];
                a[mt][3] = sA[r + 8][kb + (lane & 3) + 4];
            }
#pragma unroll
            for (int nt = 0; nt < 8; nt++) {
                int nb = wn + nt * 8 + (lane >> 2);
                uint32_t b0 = sB[nb][kb + (lane & 3)];
                uint32_t b1 = sB[nb][kb + (lane & 3) + 4];
#pragma unroll
                for (int mt = 0; mt < 2; mt++) {
                    mma_tf32(acc[mt][nt], a[mt][0], a[mt][1], a[mt][2], a[mt][3], b0, b1);
                }
            }
        }
    }

    // epilogue: scatter into out (shared: plain store initializes out; routed: atomicAdd)
#pragma unroll
    for (int mt = 0; mt < 2; mt++) {
#pragma unroll
        for (int nt = 0; nt < 8; nt++) {
            int col = n0 + wn + nt * 8 + 2 * (lane & 3);
#pragma unroll
            for (int half = 0; half < 2; half++) {
                int ml = wm + mt * 16 + (lane >> 2) + half * 8;
                int r = m0 + ml;
                if (r < rows) {
                    int tok = sTok[ml];
                    float w = sW[ml];
                    float v0 = acc[mt][nt][half * 2 + 0] * w;
                    float v1 = acc[mt][nt][half * 2 + 1] * w;
                    float* dst = out + (size_t)tok * HDIM + col;
                    if (shared_mode) {
                        *(float2*)dst = make_float2(v0, v1);
                    } else {
                        atomicAdd(dst + 0, v0);
                        atomicAdd(dst + 1, v1);
                    }
                }
            }
        }
    }
}

// ---------------- launch ----------------
extern "C" void kernel_launch(void* const* d_in, const int* in_sizes, int n_in,
                              void* d_out, int out_size) {
    (void)in_sizes; (void)n_in; (void)out_size;
    const float* x    = (const float*)d_in[0];
    const float* Wg_s = (const float*)d_in[1];
    const float* Wu_s = (const float*)d_in[2];
    const float* Wd_s = (const float*)d_in[3];
    const float* Wg   = (const float*)d_in[4];
    const float* Wu   = (const float*)d_in[5];
    const float* Wd   = (const float*)d_in[6];
    const float* Wr   = (const float*)d_in[7];
    const float* rb   = (const float*)d_in[8];
    float* out = (float*)d_out;

    zero_cnt_kernel<<<1, 32>>>();
    router_kernel<<<TOKS / 8, 256>>>(x, Wr, rb);
    gateup_kernel<<<dim3(IDIM / GU_BN, TOKS / GU_BM, NE + 1), 256>>>(x, Wg_s, Wu_s, Wg, Wu);
    // shared expert writes (initializes every out element exactly once) ...
    down_kernel<<<dim3(HDIM / D_BN, TOKS / D_BM, 1), 256>>>(Wd_s, Wd, out, 1);
    // ... then routed experts accumulate
    down_kernel<<<dim3(HDIM / D_BN, TOKS / D_BM, NE), 256>>>(Wd_s, Wd, out, 0);
}

// round 3
// speedup vs baseline: 1.2705x; 1.2705x over previous
#include <cuda_runtime.h>
#include <cstdint>

#define TOKS 16384
#define HDIM 1024
#define IDIM 2048
#define NE   8
#define STG  4
#define STAGE_BYTES 20480           // A 128x20 floats (10240B) + B 128x20 floats
#define SMEM_BYTES  (STG * STAGE_BYTES)

// ---------------- static scratch ----------------
__device__ int   g_cnt[16];
__device__ int   g_off[16];
__device__ int   g_tok[NE * TOKS];
__device__ int   g_rmap[TOKS * 2];
__device__ float g_rw[TOKS * 2];
__device__ float g_xT[(size_t)TOKS * HDIM];
__device__ float g_WgsT[IDIM * HDIM];
__device__ float g_WusT[IDIM * HDIM];
__device__ float g_WdsT[HDIM * IDIM];
__device__ float g_WgT[(size_t)NE * IDIM * HDIM];
__device__ float g_WuT[(size_t)NE * IDIM * HDIM];
__device__ float g_WdT[(size_t)NE * HDIM * IDIM];
__device__ float g_hact[(size_t)3 * TOKS * IDIM];   // routed packed by g_off, shared at 2*TOKS
__device__ float g_dout[(size_t)3 * TOKS * HDIM];

// ---------------- helpers ----------------
__device__ __forceinline__ uint32_t f2tf(float f) {
    uint32_t r;
    asm("cvt.rna.tf32.f32 %0, %1;" : "=r"(r) : "f"(f));
    return r;
}

__device__ __forceinline__ uint32_t smem_u32(const void* p) {
    uint32_t a;
    asm("{ .reg .u64 t; cvta.to.shared.u64 t, %1; cvt.u32.u64 %0, t; }" : "=r"(a) : "l"(p));
    return a;
}

__device__ __forceinline__ void cp16(uint32_t dst, const float* src, int sz) {
    asm volatile("cp.async.cg.shared.global [%0], [%1], 16, %2;"
                 :: "r"(dst), "l"(src), "r"(sz) : "memory");
}
__device__ __forceinline__ void cp_commit() {
    asm volatile("cp.async.commit_group;" ::: "memory");
}
__device__ __forceinline__ void cp_wait() {
    asm volatile("cp.async.wait_group %0;" :: "n"(STG - 1) : "memory");
}

__device__ __forceinline__ void ldsm4(uint32_t* r, uint32_t addr) {
    asm volatile("ldmatrix.sync.aligned.m8n8.x4.shared.b16 {%0,%1,%2,%3}, [%4];"
                 : "=r"(r[0]), "=r"(r[1]), "=r"(r[2]), "=r"(r[3]) : "r"(addr));
}

__device__ __forceinline__ void mma_tf32(float* c, const uint32_t* a, uint32_t b0, uint32_t b1) {
    asm volatile(
        "mma.sync.aligned.m16n8k8.row.col.f32.tf32.tf32.f32 "
        "{%0,%1,%2,%3}, {%4,%5,%6,%7}, {%8,%9}, {%0,%1,%2,%3};\n"
        : "+f"(c[0]), "+f"(c[1]), "+f"(c[2]), "+f"(c[3])
        : "r"(a[0]), "r"(a[1]), "r"(a[2]), "r"(a[3]), "r"(b0), "r"(b1));
}

// ---------------- kernel: zero counters ----------------
__global__ void zero_cnt_kernel() {
    if (threadIdx.x < 16) g_cnt[threadIdx.x] = 0;
}

// ---------------- kernel: fp32 -> tf32(rna) pre-convert ----------------
__global__ void cvt_kernel(const float* __restrict__ src, int which) {
    float* dst = (which == 0) ? g_xT  : (which == 1) ? g_WgsT : (which == 2) ? g_WusT
               : (which == 3) ? g_WdsT : (which == 4) ? g_WgT  : (which == 5) ? g_WuT : g_WdT;
    size_t i = ((size_t)blockIdx.x * 256 + threadIdx.x) * 4;
    float4 v = *(const float4*)(src + i);
    v.x = __uint_as_float(f2tf(v.x));
    v.y = __uint_as_float(f2tf(v.y));
    v.z = __uint_as_float(f2tf(v.z));
    v.w = __uint_as_float(f2tf(v.w));
    *(float4*)(dst + i) = v;
}

// ---------------- kernel: router (sigmoid top-2) ----------------
__global__ void router_kernel(const float* __restrict__ x,
                              const float* __restrict__ Wr,
                              const float* __restrict__ rb) {
    __shared__ float sWr[NE][HDIM];
    int tid = threadIdx.x;
    for (int i = tid * 4; i < NE * HDIM; i += blockDim.x * 4)
        *(float4*)&sWr[0][i] = *(const float4*)&Wr[i];
    __syncthreads();

    int wid = tid >> 5, lane = tid & 31;
    int t = blockIdx.x * 8 + wid;
    const float* xr = x + (size_t)t * HDIM;

    float acc[NE];
#pragma unroll
    for (int e = 0; e < NE; e++) acc[e] = 0.f;
    for (int k = lane; k < HDIM; k += 32) {
        float xv = xr[k];
#pragma unroll
        for (int e = 0; e < NE; e++) acc[e] += xv * sWr[e][k];
    }
#pragma unroll
    for (int e = 0; e < NE; e++) {
#pragma unroll
        for (int off = 16; off > 0; off >>= 1)
            acc[e] += __shfl_xor_sync(0xffffffffu, acc[e], off);
    }
    if (lane == 0) {
        float best1 = -1e30f, best2 = -1e30f;
        int e1 = -1, e2 = -1;
#pragma unroll
        for (int e = 0; e < NE; e++) {
            float l = acc[e] + rb[e];
            if (l > best1) { best2 = best1; e2 = e1; best1 = l; e1 = e; }
            else if (l > best2) { best2 = l; e2 = e; }
        }
        float w1 = 1.f / (1.f + __expf(-best1));
        float w2 = 1.f / (1.f + __expf(-best2));
        int p1 = atomicAdd(&g_cnt[e1], 1);
        g_tok[e1 * TOKS + p1] = t;
        g_rmap[t * 2 + 0] = (e1 << 24) | p1;  g_rw[t * 2 + 0] = w1;
        int p2 = atomicAdd(&g_cnt[e2], 1);
        g_tok[e2 * TOKS + p2] = t;
        g_rmap[t * 2 + 1] = (e2 << 24) | p2;  g_rw[t * 2 + 1] = w2;
    }
}

// ---------------- kernel: prefix offsets ----------------
__global__ void offs_kernel() {
    if (threadIdx.x == 0) {
        int a = 0;
        for (int e = 0; e < NE; e++) { g_off[e] = a; a += g_cnt[e]; }
        g_off[NE] = 2 * TOKS;
    }
}

// ========== gate+up GEMM: BM=128, 64 out-cols (gate+up interleaved in BN=128) ==========
__global__ __launch_bounds__(256) void gateup_kernel() {
    extern __shared__ float smem[];
    __shared__ int sTok[128];
    const uint32_t sb = smem_u32(smem);
    const int e = blockIdx.z;
    const int rows = (e == NE) ? TOKS : g_cnt[e];
    const int m0 = blockIdx.y * 128;
    if (m0 >= rows) return;
    const int n0 = blockIdx.x * 64;
    const float* Bg = (e == NE) ? g_WgsT : g_WgT + (size_t)e * IDIM * HDIM;
    const float* Bu = (e == NE) ? g_WusT : g_WuT + (size_t)e * IDIM * HDIM;
    const int rowbase = g_off[e];
    const int tid = threadIdx.x, wid = tid >> 5, lane = tid & 31;
    const int wm = (wid & 3) * 32, wn = (wid >> 2) * 64;

    for (int m = tid; m < 128; m += 256) {
        int r = m0 + m;
        sTok[m] = (r < rows) ? ((e == NE) ? r : g_tok[e * TOKS + r]) : -1;
    }
    __syncthreads();

    // per-thread fill descriptors (2 x 16B for A, 2 x 16B for B per stage)
    const float* asrc[2]; int asz[2]; uint32_t aoff[2];
    const float* bsrc[2]; uint32_t boff[2];
#pragma unroll
    for (int i = 0; i < 2; i++) {
        int idx = tid + i * 256;
        int m = idx >> 2, kc = (idx & 3) * 4;
        int tok = sTok[m];
        asrc[i] = g_xT + (tok >= 0 ? (size_t)tok * HDIM : 0) + kc;
        asz[i]  = (tok >= 0) ? 16 : 0;
        aoff[i] = (m * 20 + kc) * 4;
        int n = m;
        int mat = (n >> 5) & 1;
        int col = n0 + ((n >> 6) << 5) + (n & 31);
        bsrc[i] = (mat ? Bu : Bg) + (size_t)col * HDIM + kc;
        boff[i] = 10240 + (n * 20 + kc) * 4;
    }

    float acc[2][8][4];
#pragma unroll
    for (int mt = 0; mt < 2; mt++)
#pragma unroll
        for (int nt = 0; nt < 8; nt++)
#pragma unroll
            for (int i = 0; i < 4; i++) acc[mt][nt][i] = 0.f;

    const int KT = HDIM / 16;
    int fetch = 0;
#pragma unroll
    for (; fetch < STG - 1; fetch++) {
        uint32_t st = sb + fetch * STAGE_BYTES;
#pragma unroll
        for (int i = 0; i < 2; i++) cp16(st + aoff[i], asrc[i] + fetch * 16, asz[i]);
#pragma unroll
        for (int i = 0; i < 2; i++) cp16(st + boff[i], bsrc[i] + fetch * 16, 16);
        cp_commit();
    }

    for (int c = 0; c < KT; c++) {
        if (fetch < KT) {
            uint32_t st = sb + (fetch % STG) * STAGE_BYTES;
#pragma unroll
            for (int i = 0; i < 2; i++) cp16(st + aoff[i], asrc[i] + fetch * 16, asz[i]);
#pragma unroll
            for (int i = 0; i < 2; i++) cp16(st + boff[i], bsrc[i] + fetch * 16, 16);
            fetch++;
        }
        cp_commit();
        cp_wait();
        __syncthreads();

        const uint32_t Ab = sb + (c % STG) * STAGE_BYTES;
        const uint32_t Bb = Ab + 10240;
#pragma unroll
        for (int ks = 0; ks < 2; ks++) {
            const int kb = ks * 8;
            uint32_t a[2][4];
#pragma unroll
            for (int mt = 0; mt < 2; mt++) {
                int row = wm + mt * 16 + (lane & 7) + ((lane >> 3) & 1) * 8;
                int col = kb + ((lane >> 4) & 1) * 4;
                ldsm4(a[mt], Ab + (row * 20 + col) * 4);
            }
            uint32_t b[8][2];
#pragma unroll
            for (int p = 0; p < 4; p++) {
                int row = wn + p * 16 + (lane & 7) + ((lane >> 4) & 1) * 8;
                int col = kb + ((lane >> 3) & 1) * 4;
                uint32_t t[4];
                ldsm4(t, Bb + (row * 20 + col) * 4);
                b[2 * p][0] = t[0]; b[2 * p][1] = t[1];
                b[2 * p + 1][0] = t[2]; b[2 * p + 1][1] = t[3];
            }
#pragma unroll
            for (int nt = 0; nt < 8; nt++)
#pragma unroll
                for (int mt = 0; mt < 2; mt++)
                    mma_tf32(acc[mt][nt], a[mt], b[nt][0], b[nt][1]);
        }
        __syncthreads();
    }

    // epilogue: h = silu(g)*u, pre-rounded to tf32
    const int cb = n0 + (wn >> 1);
#pragma unroll
    for (int mt = 0; mt < 2; mt++) {
#pragma unroll
        for (int h = 0; h < 2; h++) {
            int r = m0 + wm + mt * 16 + (lane >> 2) + h * 8;
            if (r < rows) {
                float* hrow = g_hact + (size_t)(rowbase + r) * IDIM;
#pragma unroll
                for (int nt = 0; nt < 4; nt++) {
                    int col = cb + nt * 8 + 2 * (lane & 3);
                    float g0 = acc[mt][nt][h * 2 + 0], g1 = acc[mt][nt][h * 2 + 1];
                    float u0 = acc[mt][nt + 4][h * 2 + 0], u1 = acc[mt][nt + 4][h * 2 + 1];
                    float h0 = g0 * u0 / (1.f + __expf(-g0));
                    float h1 = g1 * u1 / (1.f + __expf(-g1));
                    float2 o;
                    o.x = __uint_as_float(f2tf(h0));
                    o.y = __uint_as_float(f2tf(h1));
                    *(float2*)(hrow + col) = o;
                }
            }
        }
    }
}

// ========== down GEMM: BM=128, BN=128 over HDIM, K over IDIM ==========
__global__ __launch_bounds__(256) void down_kernel() {
    extern __shared__ float smem[];
    const uint32_t sb = smem_u32(smem);
    const int e = blockIdx.z;
    const int rows = (e == NE) ? TOKS : g_cnt[e];
    const int m0 = blockIdx.y * 128;
    if (m0 >= rows) return;
    const int n0 = blockIdx.x * 128;
    const float* Bw = (e == NE) ? g_WdsT : g_WdT + (size_t)e * HDIM * IDIM;
    const int rowbase = g_off[e];
    const int tid = threadIdx.x, wid = tid >> 5, lane = tid & 31;
    const int wm = (wid & 3) * 32, wn = (wid >> 2) * 64;

    const float* asrc[2]; uint32_t aoff[2];
    const float* bsrc[2]; uint32_t boff[2];
#pragma unroll
    for (int i = 0; i < 2; i++) {
        int idx = tid + i * 256;
        int m = idx >> 2, kc = (idx & 3) * 4;
        asrc[i] = g_hact + (size_t)(rowbase + m0 + m) * IDIM + kc;
        aoff[i] = (m * 20 + kc) * 4;
        bsrc[i] = Bw + (size_t)(n0 + m) * IDIM + kc;
        boff[i] = 10240 + (m * 20 + kc) * 4;
    }

    float acc[2][8][4];
#pragma unroll
    for (int mt = 0; mt < 2; mt++)
#pragma unroll
        for (int nt = 0; nt < 8; nt++)
#pragma unroll
            for (int i = 0; i < 4; i++) acc[mt][nt][i] = 0.f;

    const int KT = IDIM / 16;
    int fetch = 0;
#pragma unroll
    for (; fetch < STG - 1; fetch++) {
        uint32_t st = sb + fetch * STAGE_BYTES;
#pragma unroll
        for (int i = 0; i < 2; i++) cp16(st + aoff[i], asrc[i] + fetch * 16, 16);
#pragma unroll
        for (int i = 0; i < 2; i++) cp16(st + boff[i], bsrc[i] + fetch * 16, 16);
        cp_commit();
    }

    for (int c = 0; c < KT; c++) {
        if (fetch < KT) {
            uint32_t st = sb + (fetch % STG) * STAGE_BYTES;
#pragma unroll
            for (int i = 0; i < 2; i++) cp16(st + aoff[i], asrc[i] + fetch * 16, 16);
#pragma unroll
            for (int i = 0; i < 2; i++) cp16(st + boff[i], bsrc[i] + fetch * 16, 16);
            fetch++;
        }
        cp_commit();
        cp_wait();
        __syncthreads();

        const uint32_t Ab = sb + (c % STG) * STAGE_BYTES;
        const uint32_t Bb = Ab + 10240;
#pragma unroll
        for (int ks = 0; ks < 2; ks++) {
            const int kb = ks * 8;
            uint32_t a[2][4];
#pragma unroll
            for (int mt = 0; mt < 2; mt++) {
                int row = wm + mt * 16 + (lane & 7) + ((lane >> 3) & 1) * 8;
                int col = kb + ((lane >> 4) & 1) * 4;
                ldsm4(a[mt], Ab + (row * 20 + col) * 4);
            }
            uint32_t b[8][2];
#pragma unroll
            for (int p = 0; p < 4; p++) {
                int row = wn + p * 16 + (lane & 7) + ((lane >> 4) & 1) * 8;
                int col = kb + ((lane >> 3) & 1) * 4;
                uint32_t t[4];
                ldsm4(t, Bb + (row * 20 + col) * 4);
                b[2 * p][0] = t[0]; b[2 * p][1] = t[1];
                b[2 * p + 1][0] = t[2]; b[2 * p + 1][1] = t[3];
            }
#pragma unroll
            for (int nt = 0; nt < 8; nt++)
#pragma unroll
                for (int mt = 0; mt < 2; mt++)
                    mma_tf32(acc[mt][nt], a[mt], b[nt][0], b[nt][1]);
        }
        __syncthreads();
    }

#pragma unroll
    for (int mt = 0; mt < 2; mt++) {
#pragma unroll
        for (int h = 0; h < 2; h++) {
            int r = m0 + wm + mt * 16 + (lane >> 2) + h * 8;
            if (r < rows) {
                float* drow = g_dout + (size_t)(rowbase + r) * HDIM;
#pragma unroll
                for (int nt = 0; nt < 8; nt++) {
                    int col = n0 + wn + nt * 8 + 2 * (lane & 3);
                    float2 o;
                    o.x = acc[mt][nt][h * 2 + 0];
                    o.y = acc[mt][nt][h * 2 + 1];
                    *(float2*)(drow + col) = o;
                }
            }
        }
    }
}

// ---------------- kernel: final combine ----------------
__global__ void combine_kernel(float* __restrict__ out) {
    int t = blockIdx.x;
    int h4 = threadIdx.x * 4;
    int v1 = g_rmap[t * 2 + 0], v2 = g_rmap[t * 2 + 1];
    float w1 = g_rw[t * 2 + 0], w2 = g_rw[t * 2 + 1];
    int m1 = g_off[v1 >> 24] + (v1 & 0xFFFFFF);
    int m2 = g_off[v2 >> 24] + (v2 & 0xFFFFFF);
    float4 s = *(const float4*)(g_dout + (size_t)(2 * TOKS + t) * HDIM + h4);
    float4 a = *(const float4*)(g_dout + (size_t)m1 * HDIM + h4);
    float4 b = *(const float4*)(g_dout + (size_t)m2 * HDIM + h4);
    float4 o;
    o.x = s.x + w1 * a.x + w2 * b.x;
    o.y = s.y + w1 * a.y + w2 * b.y;
    o.z = s.z + w1 * a.z + w2 * b.z;
    o.w = s.w + w1 * a.w + w2 * b.w;
    *(float4*)(out + (size_t)t * HDIM + h4) = o;
}

// ---------------- launch ----------------
extern "C" void kernel_launch(void* const* d_in, const int* in_sizes, int n_in,
                              void* d_out, int out_size) {
    (void)in_sizes; (void)n_in; (void)out_size;
    const float* x    = (const float*)d_in[0];
    const float* Wg_s = (const float*)d_in[1];
    const float* Wu_s = (const float*)d_in[2];
    const float* Wd_s = (const float*)d_in[3];
    const float* Wg   = (const float*)d_in[4];
    const float* Wu   = (const float*)d_in[5];
    const float* Wd   = (const float*)d_in[6];
    const float* Wr   = (const float*)d_in[7];
    const float* rb   = (const float*)d_in[8];
    float* out = (float*)d_out;

    cudaFuncSetAttribute(gateup_kernel, cudaFuncAttributeMaxDynamicSharedMemorySize, SMEM_BYTES);
    cudaFuncSetAttribute(down_kernel,   cudaFuncAttributeMaxDynamicSharedMemorySize, SMEM_BYTES);

    zero_cnt_kernel<<<1, 32>>>();
    cvt_kernel<<<TOKS * HDIM / 1024, 256>>>(x, 0);
    cvt_kernel<<<IDIM * HDIM / 1024, 256>>>(Wg_s, 1);
    cvt_kernel<<<IDIM * HDIM / 1024, 256>>>(Wu_s, 2);
    cvt_kernel<<<HDIM * IDIM / 1024, 256>>>(Wd_s, 3);
    cvt_kernel<<<NE * IDIM * HDIM / 1024, 256>>>(Wg, 4);
    cvt_kernel<<<NE * IDIM * HDIM / 1024, 256>>>(Wu, 5);
    cvt_kernel<<<NE * HDIM * IDIM / 1024, 256>>>(Wd, 6);
    router_kernel<<<TOKS / 8, 256>>>(x, Wr, rb);
    offs_kernel<<<1, 32>>>();
    gateup_kernel<<<dim3(IDIM / 64, TOKS / 128, NE + 1), 256, SMEM_BYTES>>>();
    down_kernel<<<dim3(HDIM / 128, TOKS / 128, NE + 1), 256, SMEM_BYTES>>>();
    combine_kernel<<<TOKS, 256>>>(out);
}

// round 4
// speedup vs baseline: 1.6113x; 1.2682x over previous
#include <cuda_runtime.h>
#include <cuda_fp16.h>
#include <cstdint>

#define TOKS 16384
#define HDIM 1024
#define IDIM 2048
#define NE   8
#define STG  4
#define STAGE_BYTES 16384           // A: 4 chunks x 128 rows x 16B = 8KB, B same
#define SMEM_BYTES  (STG * STAGE_BYTES)

// ---------------- static scratch ----------------
__device__ int   g_cnt[16];
__device__ int   g_off[16];
__device__ int   g_tok[NE * TOKS];
__device__ int   g_rmap[TOKS * 2];
__device__ float g_rw[TOKS * 2];
__device__ __align__(256) __half g_xh[(size_t)TOKS * HDIM];
__device__ __align__(256) __half g_Wgh[(size_t)(NE + 1) * IDIM * HDIM];  // slot NE = shared
__device__ __align__(256) __half g_Wuh[(size_t)(NE + 1) * IDIM * HDIM];
__device__ __align__(256) __half g_Wdh[(size_t)(NE + 1) * HDIM * IDIM];
__device__ __align__(256) __half g_hh[(size_t)3 * TOKS * IDIM];  // routed packed, shared at 2*TOKS
__device__ __align__(256) float  g_dout[(size_t)3 * TOKS * HDIM];

// ---------------- helpers ----------------
__device__ __forceinline__ uint32_t smem_u32(const void* p) {
    uint32_t a;
    asm("{ .reg .u64 t; cvta.to.shared.u64 t, %1; cvt.u32.u64 %0, t; }" : "=r"(a) : "l"(p));
    return a;
}
__device__ __forceinline__ void cp16(uint32_t dst, const __half* src, int sz) {
    asm volatile("cp.async.cg.shared.global [%0], [%1], 16, %2;"
                 :: "r"(dst), "l"(src), "r"(sz) : "memory");
}
__device__ __forceinline__ void cp_commit() { asm volatile("cp.async.commit_group;" ::: "memory"); }
__device__ __forceinline__ void cp_wait()   { asm volatile("cp.async.wait_group %0;" :: "n"(STG - 1) : "memory"); }

__device__ __forceinline__ void ldsm4(uint32_t* r, uint32_t addr) {
    asm volatile("ldmatrix.sync.aligned.m8n8.x4.shared.b16 {%0,%1,%2,%3}, [%4];"
                 : "=r"(r[0]), "=r"(r[1]), "=r"(r[2]), "=r"(r[3]) : "r"(addr));
}
__device__ __forceinline__ void mma_f16(float* c, const uint32_t* a, uint32_t b0, uint32_t b1) {
    asm volatile(
        "mma.sync.aligned.m16n8k16.row.col.f32.f16.f16.f32 "
        "{%0,%1,%2,%3}, {%4,%5,%6,%7}, {%8,%9}, {%0,%1,%2,%3};\n"
        : "+f"(c[0]), "+f"(c[1]), "+f"(c[2]), "+f"(c[3])
        : "r"(a[0]), "r"(a[1]), "r"(a[2]), "r"(a[3]), "r"(b0), "r"(b1));
}

// ---------------- kernel: zero counters ----------------
__global__ void zero_cnt_kernel() {
    if (threadIdx.x < 16) g_cnt[threadIdx.x] = 0;
}

// ---------------- kernel: fp32 -> fp16 pre-convert (8 elems/thread) ----------------
__global__ void cvt_kernel(const float* __restrict__ src, int which) {
    __half* dst = (which == 0) ? g_xh
                : (which == 1) ? g_Wgh + (size_t)NE * IDIM * HDIM
                : (which == 2) ? g_Wuh + (size_t)NE * IDIM * HDIM
                : (which == 3) ? g_Wdh + (size_t)NE * HDIM * IDIM
                : (which == 4) ? g_Wgh
                : (which == 5) ? g_Wuh
                :                g_Wdh;
    size_t i = ((size_t)blockIdx.x * 256 + threadIdx.x) * 8;
    float4 v0 = *(const float4*)(src + i);
    float4 v1 = *(const float4*)(src + i + 4);
    __half2 h[4];
    h[0] = __floats2half2_rn(v0.x, v0.y);
    h[1] = __floats2half2_rn(v0.z, v0.w);
    h[2] = __floats2half2_rn(v1.x, v1.y);
    h[3] = __floats2half2_rn(v1.z, v1.w);
    *(uint4*)(dst + i) = *(uint4*)h;
}

// ---------------- kernel: router (sigmoid top-2) ----------------
__global__ void router_kernel(const float* __restrict__ x,
                              const float* __restrict__ Wr,
                              const float* __restrict__ rb) {
    __shared__ float sWr[NE][HDIM];
    int tid = threadIdx.x;
    for (int i = tid * 4; i < NE * HDIM; i += blockDim.x * 4)
        *(float4*)&sWr[0][i] = *(const float4*)&Wr[i];
    __syncthreads();

    int wid = tid >> 5, lane = tid & 31;
    int t = blockIdx.x * 8 + wid;
    const float* xr = x + (size_t)t * HDIM;

    float acc[NE];
#pragma unroll
    for (int e = 0; e < NE; e++) acc[e] = 0.f;
    for (int k = lane; k < HDIM; k += 32) {
        float xv = xr[k];
#pragma unroll
        for (int e = 0; e < NE; e++) acc[e] += xv * sWr[e][k];
    }
#pragma unroll
    for (int e = 0; e < NE; e++) {
#pragma unroll
        for (int off = 16; off > 0; off >>= 1)
            acc[e] += __shfl_xor_sync(0xffffffffu, acc[e], off);
    }
    if (lane == 0) {
        float best1 = -1e30f, best2 = -1e30f;
        int e1 = -1, e2 = -1;
#pragma unroll
        for (int e = 0; e < NE; e++) {
            float l = acc[e] + rb[e];
            if (l > best1) { best2 = best1; e2 = e1; best1 = l; e1 = e; }
            else if (l > best2) { best2 = l; e2 = e; }
        }
        float w1 = 1.f / (1.f + __expf(-best1));
        float w2 = 1.f / (1.f + __expf(-best2));
        int p1 = atomicAdd(&g_cnt[e1], 1);
        g_tok[e1 * TOKS + p1] = t;
        g_rmap[t * 2 + 0] = (e1 << 24) | p1;  g_rw[t * 2 + 0] = w1;
        int p2 = atomicAdd(&g_cnt[e2], 1);
        g_tok[e2 * TOKS + p2] = t;
        g_rmap[t * 2 + 1] = (e2 << 24) | p2;  g_rw[t * 2 + 1] = w2;
    }
}

// ---------------- kernel: prefix offsets ----------------
__global__ void offs_kernel() {
    if (threadIdx.x == 0) {
        int a = 0;
        for (int e = 0; e < NE; e++) { g_off[e] = a; a += g_cnt[e]; }
        g_off[NE] = 2 * TOKS;
    }
}

// smem layout per stage: chunk-major, 16B chunks: A at (c*128+m)*16, B at 8192 + (c*128+n)*16
// ========== gate+up GEMM: BM=128 tokens, 64 out-cols (gate+up interleaved) ==========
__global__ __launch_bounds__(256) void gateup_kernel() {
    extern __shared__ char smem[];
    __shared__ int sTok[128];
    const uint32_t sb = smem_u32(smem);
    const int e = blockIdx.z;
    const int rows = (e == NE) ? TOKS : g_cnt[e];
    const int m0 = blockIdx.y * 128;
    if (m0 >= rows) return;
    const int n0 = blockIdx.x * 64;
    const __half* Bg = g_Wgh + (size_t)e * IDIM * HDIM;
    const __half* Bu = g_Wuh + (size_t)e * IDIM * HDIM;
    const int rowbase = g_off[e];
    const int tid = threadIdx.x, wid = tid >> 5, lane = tid & 31;
    const int wm = (wid & 3) * 32, wn = (wid >> 2) * 64;

    for (int m = tid; m < 128; m += 256) {
        int r = m0 + m;
        sTok[m] = (r < rows) ? ((e == NE) ? r : g_tok[e * TOKS + r]) : -1;
    }
    __syncthreads();

    // per-thread fill: 2 A chunks + 2 B chunks per stage
    const __half* asrc[2]; int asz[2]; uint32_t aoff[2];
    const __half* bsrc[2]; uint32_t boff[2];
#pragma unroll
    for (int i = 0; i < 2; i++) {
        int idx = tid + i * 256;
        int c = idx & 3, m = idx >> 2;
        int tok = sTok[m];
        asrc[i] = g_xh + (tok >= 0 ? (size_t)tok * HDIM : 0) + c * 8;
        asz[i]  = (tok >= 0) ? 16 : 0;
        aoff[i] = (uint32_t)(c * 128 + m) * 16;
        int n = m;
        int mat = (n >> 5) & 1;
        int col = n0 + ((n >> 6) << 5) + (n & 31);
        bsrc[i] = (mat ? Bu : Bg) + (size_t)col * HDIM + c * 8;
        boff[i] = 8192u + (uint32_t)(c * 128 + n) * 16;
    }

    float acc[2][8][4];
#pragma unroll
    for (int mt = 0; mt < 2; mt++)
#pragma unroll
        for (int nt = 0; nt < 8; nt++)
#pragma unroll
            for (int i = 0; i < 4; i++) acc[mt][nt][i] = 0.f;

    const int KT = HDIM / 32;
    int fetch = 0;
#pragma unroll
    for (; fetch < STG - 1; fetch++) {
        uint32_t st = sb + fetch * STAGE_BYTES;
#pragma unroll
        for (int i = 0; i < 2; i++) cp16(st + aoff[i], asrc[i] + fetch * 32, asz[i]);
#pragma unroll
        for (int i = 0; i < 2; i++) cp16(st + boff[i], bsrc[i] + fetch * 32, 16);
        cp_commit();
    }

    for (int c = 0; c < KT; c++) {
        if (fetch < KT) {
            uint32_t st = sb + (fetch % STG) * STAGE_BYTES;
#pragma unroll
            for (int i = 0; i < 2; i++) cp16(st + aoff[i], asrc[i] + fetch * 32, asz[i]);
#pragma unroll
            for (int i = 0; i < 2; i++) cp16(st + boff[i], bsrc[i] + fetch * 32, 16);
            fetch++;
        }
        cp_commit();
        cp_wait();
        __syncthreads();

        const uint32_t Ab = sb + (c % STG) * STAGE_BYTES;
        const uint32_t Bb = Ab + 8192;
#pragma unroll
        for (int s = 0; s < 2; s++) {
            const int cb = 2 * s;
            uint32_t a[2][4];
#pragma unroll
            for (int mt = 0; mt < 2; mt++) {
                int mrow = wm + mt * 16 + (lane & 7) + ((lane >> 3) & 1) * 8;
                int mc = cb + ((lane >> 4) & 1);
                ldsm4(a[mt], Ab + (uint32_t)(mc * 128 + mrow) * 16);
            }
            uint32_t b[8][2];
#pragma unroll
            for (int p = 0; p < 4; p++) {
                int nrow = wn + p * 16 + (lane & 7) + ((lane >> 4) & 1) * 8;
                int nc = cb + ((lane >> 3) & 1);
                uint32_t t[4];
                ldsm4(t, Bb + (uint32_t)(nc * 128 + nrow) * 16);
                b[2 * p][0] = t[0]; b[2 * p][1] = t[1];
                b[2 * p + 1][0] = t[2]; b[2 * p + 1][1] = t[3];
            }
#pragma unroll
            for (int nt = 0; nt < 8; nt++)
#pragma unroll
                for (int mt = 0; mt < 2; mt++)
                    mma_f16(acc[mt][nt], a[mt], b[nt][0], b[nt][1]);
        }
        __syncthreads();
    }

    // epilogue: h = silu(g)*u -> half
    const int cb = n0 + (wn >> 1);
#pragma unroll
    for (int mt = 0; mt < 2; mt++) {
#pragma unroll
        for (int h = 0; h < 2; h++) {
            int r = m0 + wm + mt * 16 + (lane >> 2) + h * 8;
            if (r < rows) {
                __half* hrow = g_hh + (size_t)(rowbase + r) * IDIM;
#pragma unroll
                for (int nt = 0; nt < 4; nt++) {
                    int col = cb + nt * 8 + 2 * (lane & 3);
                    float g0 = acc[mt][nt][h * 2 + 0], g1 = acc[mt][nt][h * 2 + 1];
                    float u0 = acc[mt][nt + 4][h * 2 + 0], u1 = acc[mt][nt + 4][h * 2 + 1];
                    float h0 = g0 * u0 / (1.f + __expf(-g0));
                    float h1 = g1 * u1 / (1.f + __expf(-g1));
                    *(__half2*)(hrow + col) = __floats2half2_rn(h0, h1);
                }
            }
        }
    }
}

// ========== down GEMM: BM=128, BN=128 over HDIM, K over IDIM ==========
__global__ __launch_bounds__(256) void down_kernel() {
    extern __shared__ char smem[];
    const uint32_t sb = smem_u32(smem);
    const int e = blockIdx.z;
    const int rows = (e == NE) ? TOKS : g_cnt[e];
    const int m0 = blockIdx.y * 128;
    if (m0 >= rows) return;
    const int n0 = blockIdx.x * 128;
    const __half* Bw = g_Wdh + (size_t)e * HDIM * IDIM;
    const int rowbase = g_off[e];
    const int tid = threadIdx.x, wid = tid >> 5, lane = tid & 31;
    const int wm = (wid & 3) * 32, wn = (wid >> 2) * 64;

    const __half* asrc[2]; uint32_t aoff[2];
    const __half* bsrc[2]; uint32_t boff[2];
#pragma unroll
    for (int i = 0; i < 2; i++) {
        int idx = tid + i * 256;
        int c = idx & 3, m = idx >> 2;
        asrc[i] = g_hh + (size_t)(rowbase + m0 + m) * IDIM + c * 8;
        aoff[i] = (uint32_t)(c * 128 + m) * 16;
        bsrc[i] = Bw + (size_t)(n0 + m) * IDIM + c * 8;
        boff[i] = 8192u + (uint32_t)(c * 128 + m) * 16;
    }

    float acc[2][8][4];
#pragma unroll
    for (int mt = 0; mt < 2; mt++)
#pragma unroll
        for (int nt = 0; nt < 8; nt++)
#pragma unroll
            for (int i = 0; i < 4; i++) acc[mt][nt][i] = 0.f;

    const int KT = IDIM / 32;
    int fetch = 0;
#pragma unroll
    for (; fetch < STG - 1; fetch++) {
        uint32_t st = sb + fetch * STAGE_BYTES;
#pragma unroll
        for (int i = 0; i < 2; i++) cp16(st + aoff[i], asrc[i] + fetch * 32, 16);
#pragma unroll
        for (int i = 0; i < 2; i++) cp16(st + boff[i], bsrc[i] + fetch * 32, 16);
        cp_commit();
    }

    for (int c = 0; c < KT; c++) {
        if (fetch < KT) {
            uint32_t st = sb + (fetch % STG) * STAGE_BYTES;
#pragma unroll
            for (int i = 0; i < 2; i++) cp16(st + aoff[i], asrc[i] + fetch * 32, 16);
#pragma unroll
            for (int i = 0; i < 2; i++) cp16(st + boff[i], bsrc[i] + fetch * 32, 16);
            fetch++;
        }
        cp_commit();
        cp_wait();
        __syncthreads();

        const uint32_t Ab = sb + (c % STG) * STAGE_BYTES;
        const uint32_t Bb = Ab + 8192;
#pragma unroll
        for (int s = 0; s < 2; s++) {
            const int cb = 2 * s;
            uint32_t a[2][4];
#pragma unroll
            for (int mt = 0; mt < 2; mt++) {
                int mrow = wm + mt * 16 + (lane & 7) + ((lane >> 3) & 1) * 8;
                int mc = cb + ((lane >> 4) & 1);
                ldsm4(a[mt], Ab + (uint32_t)(mc * 128 + mrow) * 16);
            }
            uint32_t b[8][2];
#pragma unroll
            for (int p = 0; p < 4; p++) {
                int nrow = wn + p * 16 + (lane & 7) + ((lane >> 4) & 1) * 8;
                int nc = cb + ((lane >> 3) & 1);
                uint32_t t[4];
                ldsm4(t, Bb + (uint32_t)(nc * 128 + nrow) * 16);
                b[2 * p][0] = t[0]; b[2 * p][1] = t[1];
                b[2 * p + 1][0] = t[2]; b[2 * p + 1][1] = t[3];
            }
#pragma unroll
            for (int nt = 0; nt < 8; nt++)
#pragma unroll
                for (int mt = 0; mt < 2; mt++)
                    mma_f16(acc[mt][nt], a[mt], b[nt][0], b[nt][1]);
        }
        __syncthreads();
    }

#pragma unroll
    for (int mt = 0; mt < 2; mt++) {
#pragma unroll
        for (int h = 0; h < 2; h++) {
            int r = m0 + wm + mt * 16 + (lane >> 2) + h * 8;
            if (r < rows) {
                float* drow = g_dout + (size_t)(rowbase + r) * HDIM;
#pragma unroll
                for (int nt = 0; nt < 8; nt++) {
                    int col = n0 + wn + nt * 8 + 2 * (lane & 3);
                    float2 o;
                    o.x = acc[mt][nt][h * 2 + 0];
                    o.y = acc[mt][nt][h * 2 + 1];
                    *(float2*)(drow + col) = o;
                }
            }
        }
    }
}

// ---------------- kernel: final combine ----------------
__global__ void combine_kernel(float* __restrict__ out) {
    int t = blockIdx.x;
    int h4 = threadIdx.x * 4;
    int v1 = g_rmap[t * 2 + 0], v2 = g_rmap[t * 2 + 1];
    float w1 = g_rw[t * 2 + 0], w2 = g_rw[t * 2 + 1];
    int m1 = g_off[v1 >> 24] + (v1 & 0xFFFFFF);
    int m2 = g_off[v2 >> 24] + (v2 & 0xFFFFFF);
    float4 s = *(const float4*)(g_dout + (size_t)(2 * TOKS + t) * HDIM + h4);
    float4 a = *(const float4*)(g_dout + (size_t)m1 * HDIM + h4);
    float4 b = *(const float4*)(g_dout + (size_t)m2 * HDIM + h4);
    float4 o;
    o.x = s.x + w1 * a.x + w2 * b.x;
    o.y = s.y + w1 * a.y + w2 * b.y;
    o.z = s.z + w1 * a.z + w2 * b.z;
    o.w = s.w + w1 * a.w + w2 * b.w;
    *(float4*)(out + (size_t)t * HDIM + h4) = o;
}

// ---------------- launch ----------------
extern "C" void kernel_launch(void* const* d_in, const int* in_sizes, int n_in,
                              void* d_out, int out_size) {
    (void)in_sizes; (void)n_in; (void)out_size;
    const float* x    = (const float*)d_in[0];
    const float* Wg_s = (const float*)d_in[1];
    const float* Wu_s = (const float*)d_in[2];
    const float* Wd_s = (const float*)d_in[3];
    const float* Wg   = (const float*)d_in[4];
    const float* Wu   = (const float*)d_in[5];
    const float* Wd   = (const float*)d_in[6];
    const float* Wr   = (const float*)d_in[7];
    const float* rb   = (const float*)d_in[8];
    float* out = (float*)d_out;

    cudaFuncSetAttribute(gateup_kernel, cudaFuncAttributeMaxDynamicSharedMemorySize, SMEM_BYTES);
    cudaFuncSetAttribute(down_kernel,   cudaFuncAttributeMaxDynamicSharedMemorySize, SMEM_BYTES);

    zero_cnt_kernel<<<1, 32>>>();
    cvt_kernel<<<TOKS * HDIM / 2048, 256>>>(x, 0);
    cvt_kernel<<<IDIM * HDIM / 2048, 256>>>(Wg_s, 1);
    cvt_kernel<<<IDIM * HDIM / 2048, 256>>>(Wu_s, 2);
    cvt_kernel<<<HDIM * IDIM / 2048, 256>>>(Wd_s, 3);
    cvt_kernel<<<NE * IDIM * HDIM / 2048, 256>>>(Wg, 4);
    cvt_kernel<<<NE * IDIM * HDIM / 2048, 256>>>(Wu, 5);
    cvt_kernel<<<NE * HDIM * IDIM / 2048, 256>>>(Wd, 6);
    router_kernel<<<TOKS / 8, 256>>>(x, Wr, rb);
    offs_kernel<<<1, 32>>>();
    gateup_kernel<<<dim3(IDIM / 64, TOKS / 128, NE + 1), 256, SMEM_BYTES>>>();
    down_kernel<<<dim3(HDIM / 128, TOKS / 128, NE + 1), 256, SMEM_BYTES>>>();
    combine_kernel<<<TOKS, 256>>>(out);
}

// round 5
// speedup vs baseline: 1.9236x; 1.1938x over previous
#include <cuda_runtime.h>
#include <cuda_fp16.h>
#include <cstdint>

#define TOKS 16384
#define HDIM 1024
#define IDIM 2048
#define NE   8
#define STG  4
#define STAGE_BYTES 16384           // A: 4 chunks x 128 rows x 16B = 8KB, B same
#define SMEM_BYTES  (STG * STAGE_BYTES)

// ---------------- static scratch ----------------
__device__ int   g_cnt[16];
__device__ int   g_off[16];
__device__ int   g_tok[NE * TOKS];
__device__ float g_wt [NE * TOKS];
__device__ __align__(256) __half g_xh[(size_t)TOKS * HDIM];
__device__ __align__(256) __half g_Wgh[(size_t)(NE + 1) * IDIM * HDIM];  // slot NE = shared
__device__ __align__(256) __half g_Wuh[(size_t)(NE + 1) * IDIM * HDIM];
__device__ __align__(256) __half g_Wdh[(size_t)(NE + 1) * HDIM * IDIM];
__device__ __align__(256) __half g_hh[(size_t)3 * TOKS * IDIM];  // routed packed, shared at 2*TOKS

// ---------------- helpers ----------------
__device__ __forceinline__ uint32_t smem_u32(const void* p) {
    uint32_t a;
    asm("{ .reg .u64 t; cvta.to.shared.u64 t, %1; cvt.u32.u64 %0, t; }" : "=r"(a) : "l"(p));
    return a;
}
__device__ __forceinline__ void cp16(uint32_t dst, const __half* src, int sz) {
    asm volatile("cp.async.cg.shared.global [%0], [%1], 16, %2;"
                 :: "r"(dst), "l"(src), "r"(sz) : "memory");
}
__device__ __forceinline__ void cp_commit() { asm volatile("cp.async.commit_group;" ::: "memory"); }
__device__ __forceinline__ void cp_wait()   { asm volatile("cp.async.wait_group %0;" :: "n"(STG - 2) : "memory"); }

__device__ __forceinline__ void ldsm4(uint32_t* r, uint32_t addr) {
    asm volatile("ldmatrix.sync.aligned.m8n8.x4.shared.b16 {%0,%1,%2,%3}, [%4];"
                 : "=r"(r[0]), "=r"(r[1]), "=r"(r[2]), "=r"(r[3]) : "r"(addr));
}
__device__ __forceinline__ void mma_f16(float* c, const uint32_t* a, uint32_t b0, uint32_t b1) {
    asm volatile(
        "mma.sync.aligned.m16n8k16.row.col.f32.f16.f16.f32 "
        "{%0,%1,%2,%3}, {%4,%5,%6,%7}, {%8,%9}, {%0,%1,%2,%3};\n"
        : "+f"(c[0]), "+f"(c[1]), "+f"(c[2]), "+f"(c[3])
        : "r"(a[0]), "r"(a[1]), "r"(a[2]), "r"(a[3]), "r"(b0), "r"(b1));
}

// ---------------- kernel: zero counters ----------------
__global__ void zero_cnt_kernel() {
    if (threadIdx.x < 16) g_cnt[threadIdx.x] = 0;
}

// ---------------- kernel: fp32 -> fp16 pre-convert (8 elems/thread) ----------------
__global__ void cvt_kernel(const float* __restrict__ src, int which) {
    __half* dst = (which == 0) ? g_xh
                : (which == 1) ? g_Wgh + (size_t)NE * IDIM * HDIM
                : (which == 2) ? g_Wuh + (size_t)NE * IDIM * HDIM
                : (which == 3) ? g_Wdh + (size_t)NE * HDIM * IDIM
                : (which == 4) ? g_Wgh
                : (which == 5) ? g_Wuh
                :                g_Wdh;
    size_t i = ((size_t)blockIdx.x * 256 + threadIdx.x) * 8;
    float4 v0 = *(const float4*)(src + i);
    float4 v1 = *(const float4*)(src + i + 4);
    __half2 h[4];
    h[0] = __floats2half2_rn(v0.x, v0.y);
    h[1] = __floats2half2_rn(v0.z, v0.w);
    h[2] = __floats2half2_rn(v1.x, v1.y);
    h[3] = __floats2half2_rn(v1.z, v1.w);
    *(uint4*)(dst + i) = *(uint4*)h;
}

// ---------------- kernel: router (sigmoid top-2) ----------------
__global__ void router_kernel(const float* __restrict__ x,
                              const float* __restrict__ Wr,
                              const float* __restrict__ rb) {
    __shared__ float sWr[NE][HDIM];
    int tid = threadIdx.x;
    for (int i = tid * 4; i < NE * HDIM; i += blockDim.x * 4)
        *(float4*)&sWr[0][i] = *(const float4*)&Wr[i];
    __syncthreads();

    int wid = tid >> 5, lane = tid & 31;
    int t = blockIdx.x * 8 + wid;
    const float* xr = x + (size_t)t * HDIM;

    float acc[NE];
#pragma unroll
    for (int e = 0; e < NE; e++) acc[e] = 0.f;
    for (int k = lane; k < HDIM; k += 32) {
        float xv = xr[k];
#pragma unroll
        for (int e = 0; e < NE; e++) acc[e] += xv * sWr[e][k];
    }
#pragma unroll
    for (int e = 0; e < NE; e++) {
#pragma unroll
        for (int off = 16; off > 0; off >>= 1)
            acc[e] += __shfl_xor_sync(0xffffffffu, acc[e], off);
    }
    if (lane == 0) {
        float best1 = -1e30f, best2 = -1e30f;
        int e1 = -1, e2 = -1;
#pragma unroll
        for (int e = 0; e < NE; e++) {
            float l = acc[e] + rb[e];
            if (l > best1) { best2 = best1; e2 = e1; best1 = l; e1 = e; }
            else if (l > best2) { best2 = l; e2 = e; }
        }
        float w1 = 1.f / (1.f + __expf(-best1));
        float w2 = 1.f / (1.f + __expf(-best2));
        int p1 = atomicAdd(&g_cnt[e1], 1);
        g_tok[e1 * TOKS + p1] = t;  g_wt[e1 * TOKS + p1] = w1;
        int p2 = atomicAdd(&g_cnt[e2], 1);
        g_tok[e2 * TOKS + p2] = t;  g_wt[e2 * TOKS + p2] = w2;
    }
}

// ---------------- kernel: prefix offsets ----------------
__global__ void offs_kernel() {
    if (threadIdx.x == 0) {
        int a = 0;
        for (int e = 0; e < NE; e++) { g_off[e] = a; a += g_cnt[e]; }
        g_off[NE] = 2 * TOKS;
    }
}

// smem per stage: chunk-major 16B lines: A at (c*128+m)*16, B at 8192 + (c*128+n)*16
// ========== gate+up GEMM: BM=128 tokens, 64 out-cols (gate+up interleaved) ==========
__global__ __launch_bounds__(256, 2) void gateup_kernel() {
    extern __shared__ char smem[];
    __shared__ int sTok[128];
    const uint32_t sb = smem_u32(smem);
    const int e = blockIdx.z;
    const int rows = (e == NE) ? TOKS : g_cnt[e];
    const int m0 = blockIdx.y * 128;
    if (m0 >= rows) return;
    const int n0 = blockIdx.x * 64;
    const __half* Bg = g_Wgh + (size_t)e * IDIM * HDIM;
    const __half* Bu = g_Wuh + (size_t)e * IDIM * HDIM;
    const int rowbase = g_off[e];
    const int tid = threadIdx.x, wid = tid >> 5, lane = tid & 31;
    const int wm = (wid & 3) * 32, wn = (wid >> 2) * 64;

    for (int m = tid; m < 128; m += 256) {
        int r = m0 + m;
        sTok[m] = (r < rows) ? ((e == NE) ? r : g_tok[e * TOKS + r]) : -1;
    }
    __syncthreads();

    // per-thread fill: lane-contiguous mapping m = idx&127, c = idx>>7
    const __half* asrc[2]; int asz[2]; uint32_t aoff[2];
    const __half* bsrc[2]; uint32_t boff[2];
#pragma unroll
    for (int i = 0; i < 2; i++) {
        int idx = tid + i * 256;
        int m = idx & 127, c = idx >> 7;
        int tok = sTok[m];
        asrc[i] = g_xh + (tok >= 0 ? (size_t)tok * HDIM : 0) + c * 8;
        asz[i]  = (tok >= 0) ? 16 : 0;
        aoff[i] = (uint32_t)(c * 128 + m) * 16;
        int n = m;
        int mat = (n >> 5) & 1;
        int col = n0 + ((n >> 6) << 5) + (n & 31);
        bsrc[i] = (mat ? Bu : Bg) + (size_t)col * HDIM + c * 8;
        boff[i] = 8192u + (uint32_t)(c * 128 + n) * 16;
    }

    float acc[2][8][4];
#pragma unroll
    for (int mt = 0; mt < 2; mt++)
#pragma unroll
        for (int nt = 0; nt < 8; nt++)
#pragma unroll
            for (int i = 0; i < 4; i++) acc[mt][nt][i] = 0.f;

    const int KT = HDIM / 32;
    int fetch = 0;
#pragma unroll
    for (; fetch < STG - 1; fetch++) {
        uint32_t st = sb + fetch * STAGE_BYTES;
#pragma unroll
        for (int i = 0; i < 2; i++) cp16(st + aoff[i], asrc[i] + fetch * 32, asz[i]);
#pragma unroll
        for (int i = 0; i < 2; i++) cp16(st + boff[i], bsrc[i] + fetch * 32, 16);
        cp_commit();
    }

    for (int c = 0; c < KT; c++) {
        cp_wait();
        __syncthreads();
        if (fetch < KT) {
            uint32_t st = sb + (fetch & (STG - 1)) * STAGE_BYTES;
#pragma unroll
            for (int i = 0; i < 2; i++) cp16(st + aoff[i], asrc[i] + fetch * 32, asz[i]);
#pragma unroll
            for (int i = 0; i < 2; i++) cp16(st + boff[i], bsrc[i] + fetch * 32, 16);
            fetch++;
        }
        cp_commit();

        const uint32_t Ab = sb + (c & (STG - 1)) * STAGE_BYTES;
        const uint32_t Bb = Ab + 8192;
#pragma unroll
        for (int s = 0; s < 2; s++) {
            const int cb = 2 * s;
            uint32_t a[2][4];
#pragma unroll
            for (int mt = 0; mt < 2; mt++) {
                int mrow = wm + mt * 16 + (lane & 7) + ((lane >> 3) & 1) * 8;
                int mc = cb + ((lane >> 4) & 1);
                ldsm4(a[mt], Ab + (uint32_t)(mc * 128 + mrow) * 16);
            }
            uint32_t b[8][2];
#pragma unroll
            for (int p = 0; p < 4; p++) {
                int nrow = wn + p * 16 + (lane & 7) + ((lane >> 4) & 1) * 8;
                int nc = cb + ((lane >> 3) & 1);
                uint32_t t[4];
                ldsm4(t, Bb + (uint32_t)(nc * 128 + nrow) * 16);
                b[2 * p][0] = t[0]; b[2 * p][1] = t[1];
                b[2 * p + 1][0] = t[2]; b[2 * p + 1][1] = t[3];
            }
#pragma unroll
            for (int nt = 0; nt < 8; nt++)
#pragma unroll
                for (int mt = 0; mt < 2; mt++)
                    mma_f16(acc[mt][nt], a[mt], b[nt][0], b[nt][1]);
        }
    }

    // epilogue: h = silu(g)*u -> half
    const int cb = n0 + (wn >> 1);
#pragma unroll
    for (int mt = 0; mt < 2; mt++) {
#pragma unroll
        for (int h = 0; h < 2; h++) {
            int r = m0 + wm + mt * 16 + (lane >> 2) + h * 8;
            if (r < rows) {
                __half* hrow = g_hh + (size_t)(rowbase + r) * IDIM;
#pragma unroll
                for (int nt = 0; nt < 4; nt++) {
                    int col = cb + nt * 8 + 2 * (lane & 3);
                    float g0 = acc[mt][nt][h * 2 + 0], g1 = acc[mt][nt][h * 2 + 1];
                    float u0 = acc[mt][nt + 4][h * 2 + 0], u1 = acc[mt][nt + 4][h * 2 + 1];
                    float h0 = g0 * u0 / (1.f + __expf(-g0));
                    float h1 = g1 * u1 / (1.f + __expf(-g1));
                    *(__half2*)(hrow + col) = __floats2half2_rn(h0, h1);
                }
            }
        }
    }
}

// ========== down GEMM: BM=128, BN=128 over HDIM, K over IDIM ==========
// shared_mode=1: e=NE, plain stores to out (full init). shared_mode=0: weighted atomicAdd.
__global__ __launch_bounds__(256, 2) void down_kernel(float* __restrict__ out, int shared_mode) {
    extern __shared__ char smem[];
    __shared__ int   sTok[128];
    __shared__ float sW[128];
    const uint32_t sb = smem_u32(smem);
    const int e = shared_mode ? NE : blockIdx.z;
    const int rows = shared_mode ? TOKS : g_cnt[e];
    const int m0 = blockIdx.y * 128;
    if (m0 >= rows) return;
    const int n0 = blockIdx.x * 128;
    const __half* Bw = g_Wdh + (size_t)e * HDIM * IDIM;
    const int rowbase = shared_mode ? 2 * TOKS : g_off[e];
    const int tid = threadIdx.x, wid = tid >> 5, lane = tid & 31;
    const int wm = (wid & 3) * 32, wn = (wid >> 2) * 64;

    for (int m = tid; m < 128; m += 256) {
        int r = m0 + m;
        if (r < rows) {
            sTok[m] = shared_mode ? r : g_tok[e * TOKS + r];
            sW[m]   = shared_mode ? 1.f : g_wt[e * TOKS + r];
        } else { sTok[m] = -1; sW[m] = 0.f; }
    }
    __syncthreads();

    const __half* asrc[2]; uint32_t aoff[2];
    const __half* bsrc[2]; uint32_t boff[2];
#pragma unroll
    for (int i = 0; i < 2; i++) {
        int idx = tid + i * 256;
        int m = idx & 127, c = idx >> 7;
        asrc[i] = g_hh + (size_t)(rowbase + m0 + m) * IDIM + c * 8;
        aoff[i] = (uint32_t)(c * 128 + m) * 16;
        bsrc[i] = Bw + (size_t)(n0 + m) * IDIM + c * 8;
        boff[i] = 8192u + (uint32_t)(c * 128 + m) * 16;
    }

    float acc[2][8][4];
#pragma unroll
    for (int mt = 0; mt < 2; mt++)
#pragma unroll
        for (int nt = 0; nt < 8; nt++)
#pragma unroll
            for (int i = 0; i < 4; i++) acc[mt][nt][i] = 0.f;

    const int KT = IDIM / 32;
    int fetch = 0;
#pragma unroll
    for (; fetch < STG - 1; fetch++) {
        uint32_t st = sb + fetch * STAGE_BYTES;
#pragma unroll
        for (int i = 0; i < 2; i++) cp16(st + aoff[i], asrc[i] + fetch * 32, 16);
#pragma unroll
        for (int i = 0; i < 2; i++) cp16(st + boff[i], bsrc[i] + fetch * 32, 16);
        cp_commit();
    }

    for (int c = 0; c < KT; c++) {
        cp_wait();
        __syncthreads();
        if (fetch < KT) {
            uint32_t st = sb + (fetch & (STG - 1)) * STAGE_BYTES;
#pragma unroll
            for (int i = 0; i < 2; i++) cp16(st + aoff[i], asrc[i] + fetch * 32, 16);
#pragma unroll
            for (int i = 0; i < 2; i++) cp16(st + boff[i], bsrc[i] + fetch * 32, 16);
            fetch++;
        }
        cp_commit();

        const uint32_t Ab = sb + (c & (STG - 1)) * STAGE_BYTES;
        const uint32_t Bb = Ab + 8192;
#pragma unroll
        for (int s = 0; s < 2; s++) {
            const int cb = 2 * s;
            uint32_t a[2][4];
#pragma unroll
            for (int mt = 0; mt < 2; mt++) {
                int mrow = wm + mt * 16 + (lane & 7) + ((lane >> 3) & 1) * 8;
                int mc = cb + ((lane >> 4) & 1);
                ldsm4(a[mt], Ab + (uint32_t)(mc * 128 + mrow) * 16);
            }
            uint32_t b[8][2];
#pragma unroll
            for (int p = 0; p < 4; p++) {
                int nrow = wn + p * 16 + (lane & 7) + ((lane >> 4) & 1) * 8;
                int nc = cb + ((lane >> 3) & 1);
                uint32_t t[4];
                ldsm4(t, Bb + (uint32_t)(nc * 128 + nrow) * 16);
                b[2 * p][0] = t[0]; b[2 * p][1] = t[1];
                b[2 * p + 1][0] = t[2]; b[2 * p + 1][1] = t[3];
            }
#pragma unroll
            for (int nt = 0; nt < 8; nt++)
#pragma unroll
                for (int mt = 0; mt < 2; mt++)
                    mma_f16(acc[mt][nt], a[mt], b[nt][0], b[nt][1]);
        }
    }

    // epilogue: direct to out
#pragma unroll
    for (int mt = 0; mt < 2; mt++) {
#pragma unroll
        for (int h = 0; h < 2; h++) {
            int ml = wm + mt * 16 + (lane >> 2) + h * 8;
            int r = m0 + ml;
            if (r < rows) {
                int tok = sTok[ml];
                float w = sW[ml];
                float* drow = out + (size_t)tok * HDIM;
#pragma unroll
                for (int nt = 0; nt < 8; nt++) {
                    int col = n0 + wn + nt * 8 + 2 * (lane & 3);
                    float v0 = acc[mt][nt][h * 2 + 0];
                    float v1 = acc[mt][nt][h * 2 + 1];
                    if (shared_mode) {
                        *(float2*)(drow + col) = make_float2(v0, v1);
                    } else {
                        atomicAdd(drow + col + 0, w * v0);
                        atomicAdd(drow + col + 1, w * v1);
                    }
                }
            }
        }
    }
}

// ---------------- launch ----------------
extern "C" void kernel_launch(void* const* d_in, const int* in_sizes, int n_in,
                              void* d_out, int out_size) {
    (void)in_sizes; (void)n_in; (void)out_size;
    const float* x    = (const float*)d_in[0];
    const float* Wg_s = (const float*)d_in[1];
    const float* Wu_s = (const float*)d_in[2];
    const float* Wd_s = (const float*)d_in[3];
    const float* Wg   = (const float*)d_in[4];
    const float* Wu   = (const float*)d_in[5];
    const float* Wd   = (const float*)d_in[6];
    const float* Wr   = (const float*)d_in[7];
    const float* rb   = (const float*)d_in[8];
    float* out = (float*)d_out;

    cudaFuncSetAttribute(gateup_kernel, cudaFuncAttributeMaxDynamicSharedMemorySize, SMEM_BYTES);
    cudaFuncSetAttribute(down_kernel,   cudaFuncAttributeMaxDynamicSharedMemorySize, SMEM_BYTES);

    zero_cnt_kernel<<<1, 32>>>();
    cvt_kernel<<<TOKS * HDIM / 2048, 256>>>(x, 0);
    cvt_kernel<<<IDIM * HDIM / 2048, 256>>>(Wg_s, 1);
    cvt_kernel<<<IDIM * HDIM / 2048, 256>>>(Wu_s, 2);
    cvt_kernel<<<HDIM * IDIM / 2048, 256>>>(Wd_s, 3);
    cvt_kernel<<<NE * IDIM * HDIM / 2048, 256>>>(Wg, 4);
    cvt_kernel<<<NE * IDIM * HDIM / 2048, 256>>>(Wu, 5);
    cvt_kernel<<<NE * HDIM * IDIM / 2048, 256>>>(Wd, 6);
    router_kernel<<<TOKS / 8, 256>>>(x, Wr, rb);
    offs_kernel<<<1, 32>>>();
    gateup_kernel<<<dim3(IDIM / 64, TOKS / 128, NE + 1), 256, SMEM_BYTES>>>();
    down_kernel<<<dim3(HDIM / 128, TOKS / 128, 1), 256, SMEM_BYTES>>>(out, 1);
    down_kernel<<<dim3(HDIM / 128, TOKS / 128, NE), 256, SMEM_BYTES>>>(out, 0);
}

// round 6
// speedup vs baseline: 1.9480x; 1.0127x over previous
#include <cuda_runtime.h>
#include <cuda_fp16.h>
#include <cstdint>

#define TOKS 16384
#define HDIM 1024
#define IDIM 2048
#define NE   8
#define STG  4
#define STAGE_BYTES 24576           // A: 4 chunks x 256 rows x 16B = 16KB, B: 4 x 128 x 16B = 8KB
#define SMEM_BYTES  (STG * STAGE_BYTES)

// ---------------- static scratch ----------------
__device__ int   g_cnt[16];
__device__ int   g_off[16];
__device__ int   g_tok[NE * TOKS];
__device__ float g_wt [NE * TOKS];
__device__ __align__(256) __half g_xh[(size_t)TOKS * HDIM];
__device__ __align__(256) __half g_Wgh[(size_t)(NE + 1) * IDIM * HDIM];  // slot NE = shared
__device__ __align__(256) __half g_Wuh[(size_t)(NE + 1) * IDIM * HDIM];
__device__ __align__(256) __half g_Wdh[(size_t)(NE + 1) * HDIM * IDIM];
__device__ __align__(256) __half g_hh[(size_t)3 * TOKS * IDIM];  // routed packed, shared at 2*TOKS

// ---------------- helpers ----------------
__device__ __forceinline__ uint32_t smem_u32(const void* p) {
    uint32_t a;
    asm("{ .reg .u64 t; cvta.to.shared.u64 t, %1; cvt.u32.u64 %0, t; }" : "=r"(a) : "l"(p));
    return a;
}
__device__ __forceinline__ void cp16(uint32_t dst, const __half* src, int sz) {
    asm volatile("cp.async.cg.shared.global [%0], [%1], 16, %2;"
                 :: "r"(dst), "l"(src), "r"(sz) : "memory");
}
__device__ __forceinline__ void cp_commit() { asm volatile("cp.async.commit_group;" ::: "memory"); }
__device__ __forceinline__ void cp_wait()   { asm volatile("cp.async.wait_group %0;" :: "n"(STG - 2) : "memory"); }

__device__ __forceinline__ void ldsm4(uint32_t* r, uint32_t addr) {
    asm volatile("ldmatrix.sync.aligned.m8n8.x4.shared.b16 {%0,%1,%2,%3}, [%4];"
                 : "=r"(r[0]), "=r"(r[1]), "=r"(r[2]), "=r"(r[3]) : "r"(addr));
}
__device__ __forceinline__ void mma_f16(float* c, const uint32_t* a, uint32_t b0, uint32_t b1) {
    asm volatile(
        "mma.sync.aligned.m16n8k16.row.col.f32.f16.f16.f32 "
        "{%0,%1,%2,%3}, {%4,%5,%6,%7}, {%8,%9}, {%0,%1,%2,%3};\n"
        : "+f"(c[0]), "+f"(c[1]), "+f"(c[2]), "+f"(c[3])
        : "r"(a[0]), "r"(a[1]), "r"(a[2]), "r"(a[3]), "r"(b0), "r"(b1));
}

// ---------------- kernel: zero counters ----------------
__global__ void zero_cnt_kernel() {
    if (threadIdx.x < 16) g_cnt[threadIdx.x] = 0;
}

// ---------------- kernel: fp32 -> fp16 x convert ----------------
__global__ void cvt_x_kernel(const float* __restrict__ src) {
    size_t i = ((size_t)blockIdx.x * 256 + threadIdx.x) * 8;
    float4 v0 = *(const float4*)(src + i);
    float4 v1 = *(const float4*)(src + i + 4);
    __half2 h[4];
    h[0] = __floats2half2_rn(v0.x, v0.y);
    h[1] = __floats2half2_rn(v0.z, v0.w);
    h[2] = __floats2half2_rn(v1.x, v1.y);
    h[3] = __floats2half2_rn(v1.z, v1.w);
    *(uint4*)(g_xh + i) = *(uint4*)h;
}

// ---------------- kernel: fp32 -> fp16 weight convert (all 6 tensors, one launch) ----------------
// block ranges (2048 fp32 per block): Wgs[0,1024) Wus[1024,2048) Wds[2048,3072)
//                                     Wg[3072,11264) Wu[11264,19456) Wd[19456,27648)
__global__ void cvt_w_kernel(const float* __restrict__ Wg_s, const float* __restrict__ Wu_s,
                             const float* __restrict__ Wd_s, const float* __restrict__ Wg,
                             const float* __restrict__ Wu,   const float* __restrict__ Wd) {
    int b = blockIdx.x;
    const float* src;
    __half* dst;
    if (b < 1024)       { src = Wg_s; dst = g_Wgh + (size_t)NE * IDIM * HDIM; }
    else if (b < 2048)  { src = Wu_s; dst = g_Wuh + (size_t)NE * IDIM * HDIM; b -= 1024; }
    else if (b < 3072)  { src = Wd_s; dst = g_Wdh + (size_t)NE * HDIM * IDIM; b -= 2048; }
    else if (b < 11264) { src = Wg;   dst = g_Wgh; b -= 3072; }
    else if (b < 19456) { src = Wu;   dst = g_Wuh; b -= 11264; }
    else                { src = Wd;   dst = g_Wdh; b -= 19456; }
    size_t i = ((size_t)b * 256 + threadIdx.x) * 8;
    float4 v0 = *(const float4*)(src + i);
    float4 v1 = *(const float4*)(src + i + 4);
    __half2 h[4];
    h[0] = __floats2half2_rn(v0.x, v0.y);
    h[1] = __floats2half2_rn(v0.z, v0.w);
    h[2] = __floats2half2_rn(v1.x, v1.y);
    h[3] = __floats2half2_rn(v1.z, v1.w);
    *(uint4*)(dst + i) = *(uint4*)h;
}

// ---------------- kernel: router (sigmoid top-2) ----------------
__global__ void router_kernel(const float* __restrict__ x,
                              const float* __restrict__ Wr,
                              const float* __restrict__ rb) {
    __shared__ float sWr[NE][HDIM];
    int tid = threadIdx.x;
    for (int i = tid * 4; i < NE * HDIM; i += blockDim.x * 4)
        *(float4*)&sWr[0][i] = *(const float4*)&Wr[i];
    __syncthreads();

    int wid = tid >> 5, lane = tid & 31;
    int t = blockIdx.x * 8 + wid;
    const float* xr = x + (size_t)t * HDIM;

    float acc[NE];
#pragma unroll
    for (int e = 0; e < NE; e++) acc[e] = 0.f;
    for (int k = lane; k < HDIM; k += 32) {
        float xv = xr[k];
#pragma unroll
        for (int e = 0; e < NE; e++) acc[e] += xv * sWr[e][k];
    }
#pragma unroll
    for (int e = 0; e < NE; e++) {
#pragma unroll
        for (int off = 16; off > 0; off >>= 1)
            acc[e] += __shfl_xor_sync(0xffffffffu, acc[e], off);
    }
    if (lane == 0) {
        float best1 = -1e30f, best2 = -1e30f;
        int e1 = -1, e2 = -1;
#pragma unroll
        for (int e = 0; e < NE; e++) {
            float l = acc[e] + rb[e];
            if (l > best1) { best2 = best1; e2 = e1; best1 = l; e1 = e; }
            else if (l > best2) { best2 = l; e2 = e; }
        }
        float w1 = 1.f / (1.f + __expf(-best1));
        float w2 = 1.f / (1.f + __expf(-best2));
        int p1 = atomicAdd(&g_cnt[e1], 1);
        g_tok[e1 * TOKS + p1] = t;  g_wt[e1 * TOKS + p1] = w1;
        int p2 = atomicAdd(&g_cnt[e2], 1);
        g_tok[e2 * TOKS + p2] = t;  g_wt[e2 * TOKS + p2] = w2;
    }
}

// ---------------- kernel: prefix offsets ----------------
__global__ void offs_kernel() {
    if (threadIdx.x == 0) {
        int a = 0;
        for (int e = 0; e < NE; e++) { g_off[e] = a; a += g_cnt[e]; }
        g_off[NE] = 2 * TOKS;
    }
}

// smem per stage: A at (c*256+m)*16, B at 16384 + (c*128+n)*16
// ========== gate+up GEMM: BM=256 tokens, 64 out-cols (gate+up interleaved), 512 threads ==========
__global__ __launch_bounds__(512, 1) void gateup_kernel() {
    extern __shared__ char smem[];
    __shared__ int sTok[256];
    const uint32_t sb = smem_u32(smem);
    const int e = blockIdx.z;
    const int rows = (e == NE) ? TOKS : g_cnt[e];
    const int m0 = blockIdx.y * 256;
    if (m0 >= rows) return;
    const int n0 = blockIdx.x * 64;
    const __half* Bg = g_Wgh + (size_t)e * IDIM * HDIM;
    const __half* Bu = g_Wuh + (size_t)e * IDIM * HDIM;
    const int rowbase = g_off[e];
    const int tid = threadIdx.x, wid = tid >> 5, lane = tid & 31;
    const int wm = (wid & 7) * 32, wn = (wid >> 3) * 64;

    for (int m = tid; m < 256; m += 512) {
        int r = m0 + m;
        sTok[m] = (r < rows) ? ((e == NE) ? r : g_tok[e * TOKS + r]) : -1;
    }
    __syncthreads();

    // fill: A 1024 lines (2/thread), B 512 lines (1/thread)
    const __half* asrc[2]; int asz[2]; uint32_t aoff[2];
    const __half* bsrc; uint32_t boff;
#pragma unroll
    for (int i = 0; i < 2; i++) {
        int idx = tid + i * 512;
        int m = idx & 255, c = idx >> 8;
        int tok = sTok[m];
        asrc[i] = g_xh + (tok >= 0 ? (size_t)tok * HDIM : 0) + c * 8;
        asz[i]  = (tok >= 0) ? 16 : 0;
        aoff[i] = (uint32_t)(c * 256 + m) * 16;
    }
    {
        int n = tid & 127, c = tid >> 7;
        int mat = (n >> 5) & 1;
        int col = n0 + ((n >> 6) << 5) + (n & 31);
        bsrc = (mat ? Bu : Bg) + (size_t)col * HDIM + c * 8;
        boff = 16384u + (uint32_t)(c * 128 + n) * 16;
    }

    float acc[2][8][4];
#pragma unroll
    for (int mt = 0; mt < 2; mt++)
#pragma unroll
        for (int nt = 0; nt < 8; nt++)
#pragma unroll
            for (int i = 0; i < 4; i++) acc[mt][nt][i] = 0.f;

    const int KT = HDIM / 32;
    int fetch = 0;
#pragma unroll
    for (; fetch < STG - 1; fetch++) {
        uint32_t st = sb + fetch * STAGE_BYTES;
#pragma unroll
        for (int i = 0; i < 2; i++) cp16(st + aoff[i], asrc[i] + fetch * 32, asz[i]);
        cp16(st + boff, bsrc + fetch * 32, 16);
        cp_commit();
    }

    for (int c = 0; c < KT; c++) {
        cp_wait();
        __syncthreads();
        if (fetch < KT) {
            uint32_t st = sb + (fetch & (STG - 1)) * STAGE_BYTES;
#pragma unroll
            for (int i = 0; i < 2; i++) cp16(st + aoff[i], asrc[i] + fetch * 32, asz[i]);
            cp16(st + boff, bsrc + fetch * 32, 16);
            fetch++;
        }
        cp_commit();

        const uint32_t Ab = sb + (c & (STG - 1)) * STAGE_BYTES;
        const uint32_t Bb = Ab + 16384;
#pragma unroll
        for (int s = 0; s < 2; s++) {
            const int cb = 2 * s;
            uint32_t a[2][4];
#pragma unroll
            for (int mt = 0; mt < 2; mt++) {
                int mrow = wm + mt * 16 + (lane & 7) + ((lane >> 3) & 1) * 8;
                int mc = cb + ((lane >> 4) & 1);
                ldsm4(a[mt], Ab + (uint32_t)(mc * 256 + mrow) * 16);
            }
            uint32_t b[8][2];
#pragma unroll
            for (int p = 0; p < 4; p++) {
                int nrow = wn + p * 16 + (lane & 7) + ((lane >> 4) & 1) * 8;
                int nc = cb + ((lane >> 3) & 1);
                uint32_t t[4];
                ldsm4(t, Bb + (uint32_t)(nc * 128 + nrow) * 16);
                b[2 * p][0] = t[0]; b[2 * p][1] = t[1];
                b[2 * p + 1][0] = t[2]; b[2 * p + 1][1] = t[3];
            }
#pragma unroll
            for (int nt = 0; nt < 8; nt++)
#pragma unroll
                for (int mt = 0; mt < 2; mt++)
                    mma_f16(acc[mt][nt], a[mt], b[nt][0], b[nt][1]);
        }
    }

    // epilogue: h = silu(g)*u -> half
    const int cb = n0 + (wn >> 1);
#pragma unroll
    for (int mt = 0; mt < 2; mt++) {
#pragma unroll
        for (int h = 0; h < 2; h++) {
            int r = m0 + wm + mt * 16 + (lane >> 2) + h * 8;
            if (r < rows) {
                __half* hrow = g_hh + (size_t)(rowbase + r) * IDIM;
#pragma unroll
                for (int nt = 0; nt < 4; nt++) {
                    int col = cb + nt * 8 + 2 * (lane & 3);
                    float g0 = acc[mt][nt][h * 2 + 0], g1 = acc[mt][nt][h * 2 + 1];
                    float u0 = acc[mt][nt + 4][h * 2 + 0], u1 = acc[mt][nt + 4][h * 2 + 1];
                    float h0 = g0 * u0 / (1.f + __expf(-g0));
                    float h1 = g1 * u1 / (1.f + __expf(-g1));
                    *(__half2*)(hrow + col) = __floats2half2_rn(h0, h1);
                }
            }
        }
    }
}

// ========== down GEMM: BM=256, BN=128 over HDIM, K over IDIM, 512 threads ==========
__global__ __launch_bounds__(512, 1) void down_kernel(float* __restrict__ out, int shared_mode) {
    extern __shared__ char smem[];
    __shared__ int   sTok[256];
    __shared__ float sW[256];
    const uint32_t sb = smem_u32(smem);
    const int e = shared_mode ? NE : blockIdx.z;
    const int rows = shared_mode ? TOKS : g_cnt[e];
    const int m0 = blockIdx.y * 256;
    if (m0 >= rows) return;
    const int n0 = blockIdx.x * 128;
    const __half* Bw = g_Wdh + (size_t)e * HDIM * IDIM;
    const int rowbase = shared_mode ? 2 * TOKS : g_off[e];
    const int tid = threadIdx.x, wid = tid >> 5, lane = tid & 31;
    const int wm = (wid & 7) * 32, wn = (wid >> 3) * 64;

    for (int m = tid; m < 256; m += 512) {
        int r = m0 + m;
        if (r < rows) {
            sTok[m] = shared_mode ? r : g_tok[e * TOKS + r];
            sW[m]   = shared_mode ? 1.f : g_wt[e * TOKS + r];
        } else { sTok[m] = -1; sW[m] = 0.f; }
    }
    __syncthreads();

    const __half* asrc[2]; uint32_t aoff[2];
    const __half* bsrc; uint32_t boff;
#pragma unroll
    for (int i = 0; i < 2; i++) {
        int idx = tid + i * 512;
        int m = idx & 255, c = idx >> 8;
        asrc[i] = g_hh + (size_t)(rowbase + m0 + m) * IDIM + c * 8;
        aoff[i] = (uint32_t)(c * 256 + m) * 16;
    }
    {
        int n = tid & 127, c = tid >> 7;
        bsrc = Bw + (size_t)(n0 + n) * IDIM + c * 8;
        boff = 16384u + (uint32_t)(c * 128 + n) * 16;
    }

    float acc[2][8][4];
#pragma unroll
    for (int mt = 0; mt < 2; mt++)
#pragma unroll
        for (int nt = 0; nt < 8; nt++)
#pragma unroll
            for (int i = 0; i < 4; i++) acc[mt][nt][i] = 0.f;

    const int KT = IDIM / 32;
    int fetch = 0;
#pragma unroll
    for (; fetch < STG - 1; fetch++) {
        uint32_t st = sb + fetch * STAGE_BYTES;
#pragma unroll
        for (int i = 0; i < 2; i++) cp16(st + aoff[i], asrc[i] + fetch * 32, 16);
        cp16(st + boff, bsrc + fetch * 32, 16);
        cp_commit();
    }

    for (int c = 0; c < KT; c++) {
        cp_wait();
        __syncthreads();
        if (fetch < KT) {
            uint32_t st = sb + (fetch & (STG - 1)) * STAGE_BYTES;
#pragma unroll
            for (int i = 0; i < 2; i++) cp16(st + aoff[i], asrc[i] + fetch * 32, 16);
            cp16(st + boff, bsrc + fetch * 32, 16);
            fetch++;
        }
        cp_commit();

        const uint32_t Ab = sb + (c & (STG - 1)) * STAGE_BYTES;
        const uint32_t Bb = Ab + 16384;
#pragma unroll
        for (int s = 0; s < 2; s++) {
            const int cb = 2 * s;
            uint32_t a[2][4];
#pragma unroll
            for (int mt = 0; mt < 2; mt++) {
                int mrow = wm + mt * 16 + (lane & 7) + ((lane >> 3) & 1) * 8;
                int mc = cb + ((lane >> 4) & 1);
                ldsm4(a[mt], Ab + (uint32_t)(mc * 256 + mrow) * 16);
            }
            uint32_t b[8][2];
#pragma unroll
            for (int p = 0; p < 4; p++) {
                int nrow = wn + p * 16 + (lane & 7) + ((lane >> 4) & 1) * 8;
                int nc = cb + ((lane >> 3) & 1);
                uint32_t t[4];
                ldsm4(t, Bb + (uint32_t)(nc * 128 + nrow) * 16);
                b[2 * p][0] = t[0]; b[2 * p][1] = t[1];
                b[2 * p + 1][0] = t[2]; b[2 * p + 1][1] = t[3];
            }
#pragma unroll
            for (int nt = 0; nt < 8; nt++)
#pragma unroll
                for (int mt = 0; mt < 2; mt++)
                    mma_f16(acc[mt][nt], a[mt], b[nt][0], b[nt][1]);
        }
    }

    // epilogue: direct to out
#pragma unroll
    for (int mt = 0; mt < 2; mt++) {
#pragma unroll
        for (int h = 0; h < 2; h++) {
            int ml = wm + mt * 16 + (lane >> 2) + h * 8;
            int r = m0 + ml;
            if (r < rows) {
                int tok = sTok[ml];
                float w = sW[ml];
                float* drow = out + (size_t)tok * HDIM;
#pragma unroll
                for (int nt = 0; nt < 8; nt++) {
                    int col = n0 + wn + nt * 8 + 2 * (lane & 3);
                    float v0 = acc[mt][nt][h * 2 + 0];
                    float v1 = acc[mt][nt][h * 2 + 1];
                    if (shared_mode) {
                        *(float2*)(drow + col) = make_float2(v0, v1);
                    } else {
                        atomicAdd(drow + col + 0, w * v0);
                        atomicAdd(drow + col + 1, w * v1);
                    }
                }
            }
        }
    }
}

// ---------------- launch ----------------
extern "C" void kernel_launch(void* const* d_in, const int* in_sizes, int n_in,
                              void* d_out, int out_size) {
    (void)in_sizes; (void)n_in; (void)out_size;
    const float* x    = (const float*)d_in[0];
    const float* Wg_s = (const float*)d_in[1];
    const float* Wu_s = (const float*)d_in[2];
    const float* Wd_s = (const float*)d_in[3];
    const float* Wg   = (const float*)d_in[4];
    const float* Wu   = (const float*)d_in[5];
    const float* Wd   = (const float*)d_in[6];
    const float* Wr   = (const float*)d_in[7];
    const float* rb   = (const float*)d_in[8];
    float* out = (float*)d_out;

    cudaFuncSetAttribute(gateup_kernel, cudaFuncAttributeMaxDynamicSharedMemorySize, SMEM_BYTES);
    cudaFuncSetAttribute(down_kernel,   cudaFuncAttributeMaxDynamicSharedMemorySize, SMEM_BYTES);

    zero_cnt_kernel<<<1, 32>>>();                                   // launch 1
    cvt_x_kernel<<<TOKS * HDIM / 2048, 256>>>(x);                   // launch 2
    cvt_w_kernel<<<27648, 256>>>(Wg_s, Wu_s, Wd_s, Wg, Wu, Wd);     // launch 3
    router_kernel<<<TOKS / 8, 256>>>(x, Wr, rb);                    // launch 4
    offs_kernel<<<1, 32>>>();                                       // launch 5
    gateup_kernel<<<dim3(IDIM / 64, TOKS / 256, NE + 1), 512, SMEM_BYTES>>>();   // launch 6 (profiled)
    down_kernel<<<dim3(HDIM / 128, TOKS / 256, 1), 512, SMEM_BYTES>>>(out, 1);
    down_kernel<<<dim3(HDIM / 128, TOKS / 256, NE), 512, SMEM_BYTES>>>(out, 0);
}